// round 15
// baseline (speedup 1.0000x reference)
#include <cuda_runtime.h>
#include <cuda_fp16.h>
#include <math.h>
#include <stdint.h>

// Problem constants
#define T_TOK 8192
#define H_DIM 1024
#define F_DIM 4096
#define E_NUM 8
#define C_CAP 1024

// ---------------------------------------------------------------------------
// Scratch
// ---------------------------------------------------------------------------
__device__ int    g_slot_token[E_NUM * C_CAP];
__device__ float  g_gate[T_TOK];
__device__ int    g_expert[T_TOK];
__device__ __half g_x16[(size_t)T_TOK * H_DIM];
__device__ __half g_w1[(size_t)E_NUM * H_DIM * F_DIM];
__device__ __half g_w2[(size_t)E_NUM * F_DIM * H_DIM];
__device__ __half g_hidden[(size_t)E_NUM * C_CAP * F_DIM];

// ---------------------------------------------------------------------------
// Helpers
// ---------------------------------------------------------------------------
__device__ __forceinline__ uint32_t smem_u32(const void* p) {
    uint32_t a;
    asm("{ .reg .u64 t; cvta.to.shared.u64 t, %1; cvt.u32.u64 %0, t; }" : "=r"(a) : "l"(p));
    return a;
}
__device__ __forceinline__ uint32_t h2_u32(__half2 h) {
    return *reinterpret_cast<uint32_t*>(&h);
}

#define LDSM_X4(r0, r1, r2, r3, addr) \
    asm volatile("ldmatrix.sync.aligned.m8n8.x4.shared.b16 {%0,%1,%2,%3}, [%4];" \
                 : "=r"(r0), "=r"(r1), "=r"(r2), "=r"(r3) : "r"(addr))
#define LDSM_X4_T(r0, r1, r2, r3, addr) \
    asm volatile("ldmatrix.sync.aligned.m8n8.x4.trans.shared.b16 {%0,%1,%2,%3}, [%4];" \
                 : "=r"(r0), "=r"(r1), "=r"(r2), "=r"(r3) : "r"(addr))

__device__ __forceinline__ void mma_fp16(float* d, const uint32_t* a,
                                         uint32_t b0, uint32_t b1) {
    asm volatile(
        "mma.sync.aligned.m16n8k16.row.col.f32.f16.f16.f32 "
        "{%0,%1,%2,%3},{%4,%5,%6,%7},{%8,%9},{%0,%1,%2,%3};"
        : "+f"(d[0]), "+f"(d[1]), "+f"(d[2]), "+f"(d[3])
        : "r"(a[0]), "r"(a[1]), "r"(a[2]), "r"(a[3]), "r"(b0), "r"(b1));
}

#define CP16(dst, src, sz) \
    asm volatile("cp.async.cg.shared.global [%0], [%1], 16, %2;" \
                 :: "r"(dst), "l"(src), "r"(sz))
#define CP_COMMIT() asm volatile("cp.async.commit_group;")
#define CP_WAIT1()  asm volatile("cp.async.wait_group 1;")

// SMEM stage (18 KB, identical to the proven R8 layout): A[128][80B] @0
// (80B row stride: LDSM 8-row phases conflict-free), B[32][256B] @10240
// (XOR swizzle). 6 stages; chunks loaded and consumed in PAIRS: one commit
// group = 2 chunks, one __syncthreads per 2 chunks (halves barrier count).
#define A_OFF 0
#define B_OFF 10240
#define BUF_BYTES 18432
#define STAGES 6
#define DYN_SMEM (STAGES * BUF_BYTES)   // 110592 -> 2 CTAs/SM (216 KB of 227)

// ---------------------------------------------------------------------------
// Prep: fp32 -> fp16 convert (8 elems/thread)
// ---------------------------------------------------------------------------
__global__ __launch_bounds__(256) void convh_kernel(const float* __restrict__ src,
                                                    __half* __restrict__ dst,
                                                    int n8) {
    int i = blockIdx.x * blockDim.x + threadIdx.x;
    if (i >= n8) return;
    const float4* s = reinterpret_cast<const float4*>(src) + (size_t)i * 2;
    float4 v0 = s[0], v1 = s[1];
    uint4 o;
    o.x = h2_u32(__floats2half2_rn(v0.x, v0.y));
    o.y = h2_u32(__floats2half2_rn(v0.z, v0.w));
    o.z = h2_u32(__floats2half2_rn(v1.x, v1.y));
    o.w = h2_u32(__floats2half2_rn(v1.z, v1.w));
    reinterpret_cast<uint4*>(dst)[i] = o;
}

// ---------------------------------------------------------------------------
// Gating: one warp per token
// ---------------------------------------------------------------------------
__global__ __launch_bounds__(256) void gating_kernel(const float* __restrict__ x,
                                                     const float* __restrict__ Wg) {
    int warp = (blockIdx.x * blockDim.x + threadIdx.x) >> 5;
    int lane = threadIdx.x & 31;
    if (warp >= T_TOK) return;
    const float* xr = x + (size_t)warp * H_DIM;
    float acc[8];
#pragma unroll
    for (int e = 0; e < 8; e++) acc[e] = 0.0f;
    for (int h = lane; h < H_DIM; h += 32) {
        float xv = xr[h];
        const float4* w4 = reinterpret_cast<const float4*>(Wg + (size_t)h * E_NUM);
        float4 a = w4[0], b = w4[1];
        acc[0] += xv * a.x; acc[1] += xv * a.y; acc[2] += xv * a.z; acc[3] += xv * a.w;
        acc[4] += xv * b.x; acc[5] += xv * b.y; acc[6] += xv * b.z; acc[7] += xv * b.w;
    }
#pragma unroll
    for (int e = 0; e < 8; e++)
#pragma unroll
        for (int o = 16; o > 0; o >>= 1)
            acc[e] += __shfl_down_sync(0xffffffffu, acc[e], o);
    if (lane == 0) {
        float m = acc[0]; int am = 0;
#pragma unroll
        for (int e = 1; e < 8; e++)
            if (acc[e] > m) { m = acc[e]; am = e; }
        float s = 0.0f;
#pragma unroll
        for (int e = 0; e < 8; e++) s += expf(acc[e] - m);
        g_expert[warp] = am;
        g_gate[warp]   = 1.0f / s;
    }
}

// ---------------------------------------------------------------------------
// Assign: stable per-expert prefix scan (warp-parallel) + capacity drop
// ---------------------------------------------------------------------------
__global__ __launch_bounds__(256) void assign_kernel() {
    __shared__ int cnts[256][8];
    const int tid = threadIdx.x;
    for (int i = tid; i < E_NUM * C_CAP; i += 256) g_slot_token[i] = -1;
    const int per = T_TOK / 256, base = tid * per;
    int loc[8];
#pragma unroll
    for (int e = 0; e < 8; e++) loc[e] = 0;
    for (int j = 0; j < per; j++) loc[g_expert[base + j]]++;
#pragma unroll
    for (int e = 0; e < 8; e++) cnts[tid][e] = loc[e];
    __syncthreads();
    {   // warp w scans expert w's 256 chunk counts
        const int w = tid >> 5, lane = tid & 31;
        int run = 0;
#pragma unroll
        for (int b = 0; b < 8; ++b) {
            const int idx = b * 32 + lane;
            const int v = cnts[idx][w];
            int s = v;
#pragma unroll
            for (int o = 1; o < 32; o <<= 1) {
                int t = __shfl_up_sync(0xffffffffu, s, o);
                if (lane >= o) s += t;
            }
            cnts[idx][w] = run + s - v;
            run += __shfl_sync(0xffffffffu, s, 31);
        }
    }
    __syncthreads();
#pragma unroll
    for (int e = 0; e < 8; e++) loc[e] = cnts[tid][e];
    for (int j = 0; j < per; j++) {
        int t = base + j, e = g_expert[t], s = loc[e]++;
        if (s < C_CAP) g_slot_token[e * C_CAP + s] = t;
    }
}

// ---------------------------------------------------------------------------
// Compute one 32-K chunk: plain fp16 MMA, fp32 accumulate
// ---------------------------------------------------------------------------
__device__ __forceinline__ void compute_chunk32(uint32_t bufAbs, float acc[4][4][4],
                                                int lane, int wm, int wn) {
    const uint32_t sw = (uint32_t)(lane & 7);
    const uint32_t hl = (uint32_t)(lane >> 4);
    const uint32_t aBase = bufAbs + (uint32_t)((wm * 64 + (lane & 15)) * 80);
    const uint32_t bBase = bufAbs + B_OFF + (uint32_t)((lane & 15) * 256);
#pragma unroll
    for (int k16 = 0; k16 < 2; ++k16) {
        uint32_t bh[2][4];
#pragma unroll
        for (int j2 = 0; j2 < 2; ++j2) {
            const uint32_t csw = (((uint32_t)(wn * 4 + j2 * 2) + hl) ^ sw) << 4;
            LDSM_X4_T(bh[j2][0], bh[j2][1], bh[j2][2], bh[j2][3],
                      bBase + (uint32_t)(k16 * 4096) + csw);
        }
        const uint32_t hoff = ((uint32_t)(k16 * 2) + hl) << 4;
        uint32_t ah[4][4];
#pragma unroll
        for (int i = 0; i < 4; ++i) {
            const uint32_t aoff = (uint32_t)(i * 1280) + hoff;
            LDSM_X4(ah[i][0], ah[i][1], ah[i][2], ah[i][3], aBase + aoff);
        }
#pragma unroll
        for (int i = 0; i < 4; ++i)
#pragma unroll
            for (int j = 0; j < 4; ++j) {
                const uint32_t b0 = bh[j >> 1][(j & 1) * 2];
                const uint32_t b1 = bh[j >> 1][(j & 1) * 2 + 1];
                mma_fp16(acc[i][j], ah[i], b0, b1);
            }
    }
}

// ---------------------------------------------------------------------------
// FFN1: hidden(fp16) = relu(gather(x16) @ W1[e] + b1[e])
// grid (F/128, C/128, E), 256 threads, 2 CTAs/SM, paired-chunk pipeline
// ---------------------------------------------------------------------------
__global__ __launch_bounds__(256, 2)
void ffn1_mma(const float* __restrict__ b1) {
    extern __shared__ char dynsm[];
    __shared__ int rowTok[128];

    const uint32_t sabs = smem_u32(dynsm);
    const int tid = threadIdx.x, lane = tid & 31, wid = tid >> 5;
    const int wm = wid & 1, wn = wid >> 1;
    const int e = blockIdx.z, m0 = blockIdx.y * 128, n0 = blockIdx.x * 128;

    if (tid < 128) rowTok[tid] = g_slot_token[e * C_CAP + m0 + tid];
    __syncthreads();

    const int arow = tid >> 1, ac0 = (tid & 1) * 2;
    const int atok = rowTok[arow];
    const uint32_t asz = (atok >= 0) ? 16u : 0u;
    const __half* aSrc = g_x16 + (size_t)(atok < 0 ? 0 : atok) * H_DIM + ac0 * 8;
    const uint32_t aDst = (uint32_t)(arow * 80 + ac0 * 16);

    const int bk = tid >> 3, bc0 = (tid & 7) * 2;
    const size_t wBase = (size_t)e * H_DIM * F_DIM + n0;
    const uint32_t bD0 = B_OFF + (uint32_t)(bk * 256) + ((((uint32_t)bc0)      ^ ((uint32_t)bk & 7u)) << 4);
    const uint32_t bD1 = B_OFF + (uint32_t)(bk * 256) + ((((uint32_t)bc0 + 1u) ^ ((uint32_t)bk & 7u)) << 4);

    float acc[4][4][4];
#pragma unroll
    for (int i = 0; i < 4; i++)
#pragma unroll
        for (int j = 0; j < 4; j++)
#pragma unroll
            for (int r = 0; r < 4; r++) acc[i][j][r] = 0.0f;

    const int NCH = H_DIM / 32;   // 32 chunks = 16 pairs

    auto load_stage = [&](int c) {
        const uint32_t bb = sabs + (uint32_t)((c % STAGES) * BUF_BYTES);
        const int kt = c * 32;
        CP16(bb + aDst,      aSrc + kt,     asz);
        CP16(bb + aDst + 16, aSrc + kt + 8, asz);
        const size_t wrow = wBase + (size_t)(kt + bk) * F_DIM;
        CP16(bb + bD0, g_w1 + wrow + bc0 * 8,     16u);
        CP16(bb + bD1, g_w1 + wrow + bc0 * 8 + 8, 16u);
    };

    // prologue: two pairs in flight
    load_stage(0); load_stage(1); CP_COMMIT();
    load_stage(2); load_stage(3); CP_COMMIT();

    for (int c = 0; c < NCH; c += 2) {
        CP_WAIT1();                 // pair c complete (pair c+2 may be pending)
        __syncthreads();            // all warps done reading stages (c-2, c-1)
        if (c + 4 < NCH) { load_stage(c + 4); load_stage(c + 5); }
        CP_COMMIT();
        compute_chunk32(sabs + (uint32_t)((c % STAGES) * BUF_BYTES), acc, lane, wm, wn);
        compute_chunk32(sabs + (uint32_t)(((c + 1) % STAGES) * BUF_BYTES), acc, lane, wm, wn);
    }

    // epilogue: + b1, relu, fp16 store
    const int g = lane >> 2, q = (lane & 3) * 2;
    const float* bp = b1 + (size_t)e * F_DIM + n0;
#pragma unroll
    for (int i = 0; i < 4; ++i) {
        const int r0 = m0 + wm * 64 + i * 16 + g;
        const size_t rowBase0 = ((size_t)e * C_CAP + r0) * F_DIM + n0;
        const size_t rowBase1 = rowBase0 + 8 * F_DIM;
#pragma unroll
        for (int j = 0; j < 4; ++j) {
            const int col = wn * 32 + j * 8 + q;
            const float bc0 = bp[col], bc1 = bp[col + 1];
            float v0 = fmaxf(acc[i][j][0] + bc0, 0.f);
            float v1 = fmaxf(acc[i][j][1] + bc1, 0.f);
            float v2 = fmaxf(acc[i][j][2] + bc0, 0.f);
            float v3 = fmaxf(acc[i][j][3] + bc1, 0.f);
            *reinterpret_cast<uint32_t*>(&g_hidden[rowBase0 + col]) =
                h2_u32(__floats2half2_rn(v0, v1));
            *reinterpret_cast<uint32_t*>(&g_hidden[rowBase1 + col]) =
                h2_u32(__floats2half2_rn(v2, v3));
        }
    }
}

// ---------------------------------------------------------------------------
// FFN2: out[tok] = gate * (hidden @ W2[e] + b2[e]);  K = F_DIM
// grid (H/128, C/128, E), 256 threads, 2 CTAs/SM, paired-chunk pipeline
// ---------------------------------------------------------------------------
__global__ __launch_bounds__(256, 2)
void ffn2_mma(const float* __restrict__ b2, float* __restrict__ out) {
    extern __shared__ char dynsm[];
    __shared__ int   rowTok[128];
    __shared__ float rowGate[128];

    const uint32_t sabs = smem_u32(dynsm);
    const int tid = threadIdx.x, lane = tid & 31, wid = tid >> 5;
    const int wm = wid & 1, wn = wid >> 1;
    const int e = blockIdx.z, m0 = blockIdx.y * 128, n0 = blockIdx.x * 128;

    if (tid < 128) {
        int tk = g_slot_token[e * C_CAP + m0 + tid];
        rowTok[tid]  = tk;
        rowGate[tid] = (tk >= 0) ? g_gate[tk] : 0.0f;
    }
    __syncthreads();

    const int arow = tid >> 1, ac0 = (tid & 1) * 2;
    const __half* aSrc = g_hidden + ((size_t)e * C_CAP + m0 + arow) * F_DIM + ac0 * 8;
    const uint32_t aDst = (uint32_t)(arow * 80 + ac0 * 16);

    const int bk = tid >> 3, bc0 = (tid & 7) * 2;
    const size_t wBase = (size_t)e * F_DIM * H_DIM + n0;
    const uint32_t bD0 = B_OFF + (uint32_t)(bk * 256) + ((((uint32_t)bc0)      ^ ((uint32_t)bk & 7u)) << 4);
    const uint32_t bD1 = B_OFF + (uint32_t)(bk * 256) + ((((uint32_t)bc0 + 1u) ^ ((uint32_t)bk & 7u)) << 4);

    float acc[4][4][4];
#pragma unroll
    for (int i = 0; i < 4; i++)
#pragma unroll
        for (int j = 0; j < 4; j++)
#pragma unroll
            for (int r = 0; r < 4; r++) acc[i][j][r] = 0.0f;

    const int NCH = F_DIM / 32;   // 128 chunks = 64 pairs

    auto load_stage = [&](int c) {
        const uint32_t bb = sabs + (uint32_t)((c % STAGES) * BUF_BYTES);
        const int kt = c * 32;
        CP16(bb + aDst,      aSrc + kt,     16u);
        CP16(bb + aDst + 16, aSrc + kt + 8, 16u);
        const size_t wrow = wBase + (size_t)(kt + bk) * H_DIM;
        CP16(bb + bD0, g_w2 + wrow + bc0 * 8,     16u);
        CP16(bb + bD1, g_w2 + wrow + bc0 * 8 + 8, 16u);
    };

    load_stage(0); load_stage(1); CP_COMMIT();
    load_stage(2); load_stage(3); CP_COMMIT();

    for (int c = 0; c < NCH; c += 2) {
        CP_WAIT1();
        __syncthreads();
        if (c + 4 < NCH) { load_stage(c + 4); load_stage(c + 5); }
        CP_COMMIT();
        compute_chunk32(sabs + (uint32_t)((c % STAGES) * BUF_BYTES), acc, lane, wm, wn);
        compute_chunk32(sabs + (uint32_t)(((c + 1) % STAGES) * BUF_BYTES), acc, lane, wm, wn);
    }

    // epilogue: + b2, gate, scatter fp32
    const int g = lane >> 2, q = (lane & 3) * 2;
    const float* bp = b2 + (size_t)e * H_DIM + n0;
#pragma unroll
    for (int i = 0; i < 4; ++i) {
        const int rl0 = wm * 64 + i * 16 + g;
        const int rl1 = rl0 + 8;
        const int tok0 = rowTok[rl0], tok1 = rowTok[rl1];
        const float g0 = rowGate[rl0], g1 = rowGate[rl1];
#pragma unroll
        for (int j = 0; j < 4; ++j) {
            const int col = wn * 32 + j * 8 + q;
            const float bc0 = bp[col], bc1 = bp[col + 1];
            if (tok0 >= 0) {
                float2 o;
                o.x = g0 * (acc[i][j][0] + bc0);
                o.y = g0 * (acc[i][j][1] + bc1);
                *reinterpret_cast<float2*>(out + (size_t)tok0 * H_DIM + n0 + col) = o;
            }
            if (tok1 >= 0) {
                float2 o;
                o.x = g1 * (acc[i][j][2] + bc0);
                o.y = g1 * (acc[i][j][3] + bc1);
                *reinterpret_cast<float2*>(out + (size_t)tok1 * H_DIM + n0 + col) = o;
            }
        }
    }
}

// ---------------------------------------------------------------------------
// Launcher (R8 order: converts, gating, assign, ffn1, ffn2)
// ---------------------------------------------------------------------------
extern "C" void kernel_launch(void* const* d_in, const int* in_sizes, int n_in,
                              void* d_out, int out_size) {
    const float* x  = (const float*)d_in[0];
    const float* Wg = (const float*)d_in[1];
    const float* W1 = (const float*)d_in[2];
    const float* b1 = (const float*)d_in[3];
    const float* W2 = (const float*)d_in[4];
    const float* b2 = (const float*)d_in[5];
    float* out = (float*)d_out;

    cudaFuncSetAttribute(ffn1_mma, cudaFuncAttributeMaxDynamicSharedMemorySize, DYN_SMEM);
    cudaFuncSetAttribute(ffn2_mma, cudaFuncAttributeMaxDynamicSharedMemorySize, DYN_SMEM);

    cudaMemsetAsync(out, 0, (size_t)out_size * sizeof(float));

    __half *xp, *w1p, *w2p;
    cudaGetSymbolAddress((void**)&xp,  g_x16);
    cudaGetSymbolAddress((void**)&w1p, g_w1);
    cudaGetSymbolAddress((void**)&w2p, g_w2);

    const int nx = T_TOK * H_DIM / 8;
    const int nw = E_NUM * H_DIM * F_DIM / 8;
    convh_kernel<<<(nx + 255) / 256, 256>>>(x,  xp,  nx);
    convh_kernel<<<(nw + 255) / 256, 256>>>(W1, w1p, nw);
    convh_kernel<<<(nw + 255) / 256, 256>>>(W2, w2p, nw);

    gating_kernel<<<T_TOK / 8, 256>>>(x, Wg);
    assign_kernel<<<1, 256>>>();

    dim3 g1(F_DIM / 128, C_CAP / 128, E_NUM);   // (32, 8, 8)
    ffn1_mma<<<g1, 256, DYN_SMEM>>>(b1);

    dim3 g2(H_DIM / 128, C_CAP / 128, E_NUM);   // (8, 8, 8)
    ffn2_mma<<<g2, 256, DYN_SMEM>>>(b2, out);
}

// round 16
// speedup vs baseline: 1.0335x; 1.0335x over previous
#include <cuda_runtime.h>
#include <cuda_fp16.h>
#include <math.h>
#include <stdint.h>

// Problem constants
#define T_TOK 8192
#define H_DIM 1024
#define F_DIM 4096
#define E_NUM 8
#define C_CAP 1024

// ---------------------------------------------------------------------------
// Scratch
// ---------------------------------------------------------------------------
__device__ int    g_slot_token[E_NUM * C_CAP];
__device__ float  g_gate[T_TOK];
__device__ int    g_expert[T_TOK];
__device__ __half g_x16[(size_t)T_TOK * H_DIM];
__device__ __half g_w1[(size_t)E_NUM * H_DIM * F_DIM];
__device__ __half g_w2[(size_t)E_NUM * F_DIM * H_DIM];
__device__ __half g_hidden[(size_t)E_NUM * C_CAP * F_DIM];

// ---------------------------------------------------------------------------
// Helpers
// ---------------------------------------------------------------------------
__device__ __forceinline__ uint32_t smem_u32(const void* p) {
    uint32_t a;
    asm("{ .reg .u64 t; cvta.to.shared.u64 t, %1; cvt.u32.u64 %0, t; }" : "=r"(a) : "l"(p));
    return a;
}
__device__ __forceinline__ uint32_t h2_u32(__half2 h) {
    return *reinterpret_cast<uint32_t*>(&h);
}

#define LDSM_X4(r0, r1, r2, r3, addr) \
    asm volatile("ldmatrix.sync.aligned.m8n8.x4.shared.b16 {%0,%1,%2,%3}, [%4];" \
                 : "=r"(r0), "=r"(r1), "=r"(r2), "=r"(r3) : "r"(addr))
#define LDSM_X4_T(r0, r1, r2, r3, addr) \
    asm volatile("ldmatrix.sync.aligned.m8n8.x4.trans.shared.b16 {%0,%1,%2,%3}, [%4];" \
                 : "=r"(r0), "=r"(r1), "=r"(r2), "=r"(r3) : "r"(addr))

__device__ __forceinline__ void mma_fp16(float* d, const uint32_t* a,
                                         uint32_t b0, uint32_t b1) {
    asm volatile(
        "mma.sync.aligned.m16n8k16.row.col.f32.f16.f16.f32 "
        "{%0,%1,%2,%3},{%4,%5,%6,%7},{%8,%9},{%0,%1,%2,%3};"
        : "+f"(d[0]), "+f"(d[1]), "+f"(d[2]), "+f"(d[3])
        : "r"(a[0]), "r"(a[1]), "r"(a[2]), "r"(a[3]), "r"(b0), "r"(b1));
}

#define CP16(dst, src, sz) \
    asm volatile("cp.async.cg.shared.global [%0], [%1], 16, %2;" \
                 :: "r"(dst), "l"(src), "r"(sz))
#define CP_COMMIT() asm volatile("cp.async.commit_group;")
#define CP_WAIT1()  asm volatile("cp.async.wait_group 1;")

// SMEM stage (18 KB): A[128][80B] @0 (rows padded to 80B: LDSM phases
// conflict-free), B[32][256B] @10240 (XOR swizzle). 3 stages, wait_group 1.
#define A_OFF 0
#define B_OFF 10240
#define BUF_BYTES 18432
#define STAGES 3
#define DYN_SMEM (STAGES * BUF_BYTES)   // 55296

// ---------------------------------------------------------------------------
// Prep: fp32 -> fp16 convert (8 elems/thread)
// ---------------------------------------------------------------------------
__global__ __launch_bounds__(256) void convh_kernel(const float* __restrict__ src,
                                                    __half* __restrict__ dst,
                                                    int n8) {
    int i = blockIdx.x * blockDim.x + threadIdx.x;
    if (i >= n8) return;
    const float4* s = reinterpret_cast<const float4*>(src) + (size_t)i * 2;
    float4 v0 = s[0], v1 = s[1];
    uint4 o;
    o.x = h2_u32(__floats2half2_rn(v0.x, v0.y));
    o.y = h2_u32(__floats2half2_rn(v0.z, v0.w));
    o.z = h2_u32(__floats2half2_rn(v1.x, v1.y));
    o.w = h2_u32(__floats2half2_rn(v1.z, v1.w));
    reinterpret_cast<uint4*>(dst)[i] = o;
}

// ---------------------------------------------------------------------------
// Gating: one warp per token
// ---------------------------------------------------------------------------
__global__ __launch_bounds__(256) void gating_kernel(const float* __restrict__ x,
                                                     const float* __restrict__ Wg) {
    int warp = (blockIdx.x * blockDim.x + threadIdx.x) >> 5;
    int lane = threadIdx.x & 31;
    if (warp >= T_TOK) return;
    const float* xr = x + (size_t)warp * H_DIM;
    float acc[8];
#pragma unroll
    for (int e = 0; e < 8; e++) acc[e] = 0.0f;
    for (int h = lane; h < H_DIM; h += 32) {
        float xv = xr[h];
        const float4* w4 = reinterpret_cast<const float4*>(Wg + (size_t)h * E_NUM);
        float4 a = w4[0], b = w4[1];
        acc[0] += xv * a.x; acc[1] += xv * a.y; acc[2] += xv * a.z; acc[3] += xv * a.w;
        acc[4] += xv * b.x; acc[5] += xv * b.y; acc[6] += xv * b.z; acc[7] += xv * b.w;
    }
#pragma unroll
    for (int e = 0; e < 8; e++)
#pragma unroll
        for (int o = 16; o > 0; o >>= 1)
            acc[e] += __shfl_down_sync(0xffffffffu, acc[e], o);
    if (lane == 0) {
        float m = acc[0]; int am = 0;
#pragma unroll
        for (int e = 1; e < 8; e++)
            if (acc[e] > m) { m = acc[e]; am = e; }
        float s = 0.0f;
#pragma unroll
        for (int e = 0; e < 8; e++) s += expf(acc[e] - m);
        g_expert[warp] = am;
        g_gate[warp]   = 1.0f / s;
    }
}

// ---------------------------------------------------------------------------
// Assign: stable per-expert prefix scan (warp-parallel) + capacity drop
// ---------------------------------------------------------------------------
__global__ __launch_bounds__(256) void assign_kernel() {
    __shared__ int cnts[256][8];
    const int tid = threadIdx.x;
    for (int i = tid; i < E_NUM * C_CAP; i += 256) g_slot_token[i] = -1;
    const int per = T_TOK / 256, base = tid * per;
    int loc[8];
#pragma unroll
    for (int e = 0; e < 8; e++) loc[e] = 0;
    for (int j = 0; j < per; j++) loc[g_expert[base + j]]++;
#pragma unroll
    for (int e = 0; e < 8; e++) cnts[tid][e] = loc[e];
    __syncthreads();
    {   // warp w scans expert w's 256 chunk counts
        const int w = tid >> 5, lane = tid & 31;
        int run = 0;
#pragma unroll
        for (int b = 0; b < 8; ++b) {
            const int idx = b * 32 + lane;
            const int v = cnts[idx][w];
            int s = v;
#pragma unroll
            for (int o = 1; o < 32; o <<= 1) {
                int t = __shfl_up_sync(0xffffffffu, s, o);
                if (lane >= o) s += t;
            }
            cnts[idx][w] = run + s - v;
            run += __shfl_sync(0xffffffffu, s, 31);
        }
    }
    __syncthreads();
#pragma unroll
    for (int e = 0; e < 8; e++) loc[e] = cnts[tid][e];
    for (int j = 0; j < per; j++) {
        int t = base + j, e = g_expert[t], s = loc[e]++;
        if (s < C_CAP) g_slot_token[e * C_CAP + s] = t;
    }
}

// ---------------------------------------------------------------------------
// Compute one 32-K chunk: plain fp16 MMA, fp32 accumulate
// ---------------------------------------------------------------------------
__device__ __forceinline__ void compute_chunk32(uint32_t bufAbs, float acc[4][4][4],
                                                int lane, int wm, int wn) {
    const uint32_t sw = (uint32_t)(lane & 7);
    const uint32_t hl = (uint32_t)(lane >> 4);
    const uint32_t aBase = bufAbs + (uint32_t)((wm * 64 + (lane & 15)) * 80);
    const uint32_t bBase = bufAbs + B_OFF + (uint32_t)((lane & 15) * 256);
#pragma unroll
    for (int k16 = 0; k16 < 2; ++k16) {
        uint32_t bh[2][4];
#pragma unroll
        for (int j2 = 0; j2 < 2; ++j2) {
            const uint32_t csw = (((uint32_t)(wn * 4 + j2 * 2) + hl) ^ sw) << 4;
            LDSM_X4_T(bh[j2][0], bh[j2][1], bh[j2][2], bh[j2][3],
                      bBase + (uint32_t)(k16 * 4096) + csw);
        }
        const uint32_t hoff = ((uint32_t)(k16 * 2) + hl) << 4;
        uint32_t ah[4][4];
#pragma unroll
        for (int i = 0; i < 4; ++i) {
            const uint32_t aoff = (uint32_t)(i * 1280) + hoff;
            LDSM_X4(ah[i][0], ah[i][1], ah[i][2], ah[i][3], aBase + aoff);
        }
#pragma unroll
        for (int i = 0; i < 4; ++i)
#pragma unroll
            for (int j = 0; j < 4; ++j) {
                const uint32_t b0 = bh[j >> 1][(j & 1) * 2];
                const uint32_t b1 = bh[j >> 1][(j & 1) * 2 + 1];
                mma_fp16(acc[i][j], ah[i], b0, b1);
            }
    }
}

// ---------------------------------------------------------------------------
// FFN1: hidden(fp16) = relu(gather(x16) @ W1[e] + b1[e])
// grid (F/128, C/128, E), 256 threads, 2 CTAs/SM
// ---------------------------------------------------------------------------
__global__ __launch_bounds__(256, 2)
void ffn1_mma(const float* __restrict__ b1) {
    extern __shared__ char dynsm[];
    __shared__ int rowTok[128];

    const uint32_t sabs = smem_u32(dynsm);
    const int tid = threadIdx.x, lane = tid & 31, wid = tid >> 5;
    const int wm = wid & 1, wn = wid >> 1;
    const int e = blockIdx.z, m0 = blockIdx.y * 128, n0 = blockIdx.x * 128;

    if (tid < 128) rowTok[tid] = g_slot_token[e * C_CAP + m0 + tid];
    __syncthreads();

    const int arow = tid >> 1, ac0 = (tid & 1) * 2;
    const int atok = rowTok[arow];
    const uint32_t asz = (atok >= 0) ? 16u : 0u;
    const __half* aSrc = g_x16 + (size_t)(atok < 0 ? 0 : atok) * H_DIM + ac0 * 8;
    const uint32_t aDst = (uint32_t)(arow * 80 + ac0 * 16);

    const int bk = tid >> 3, bc0 = (tid & 7) * 2;
    const size_t wBase = (size_t)e * H_DIM * F_DIM + n0;
    const uint32_t bD0 = B_OFF + (uint32_t)(bk * 256) + ((((uint32_t)bc0)      ^ ((uint32_t)bk & 7u)) << 4);
    const uint32_t bD1 = B_OFF + (uint32_t)(bk * 256) + ((((uint32_t)bc0 + 1u) ^ ((uint32_t)bk & 7u)) << 4);

    float acc[4][4][4];
#pragma unroll
    for (int i = 0; i < 4; i++)
#pragma unroll
        for (int j = 0; j < 4; j++)
#pragma unroll
            for (int r = 0; r < 4; r++) acc[i][j][r] = 0.0f;

    const int NCH = H_DIM / 32;   // 32

    auto load_stage = [&](int c) {
        const uint32_t bb = sabs + (uint32_t)((c % STAGES) * BUF_BYTES);
        const int kt = c * 32;
        CP16(bb + aDst,      aSrc + kt,     asz);
        CP16(bb + aDst + 16, aSrc + kt + 8, asz);
        const size_t wrow = wBase + (size_t)(kt + bk) * F_DIM;
        CP16(bb + bD0, g_w1 + wrow + bc0 * 8,     16u);
        CP16(bb + bD1, g_w1 + wrow + bc0 * 8 + 8, 16u);
    };

    load_stage(0); CP_COMMIT();
    load_stage(1); CP_COMMIT();

    for (int c = 0; c < NCH; ++c) {
        CP_WAIT1();
        __syncthreads();
        if (c + 2 < NCH) load_stage(c + 2);
        CP_COMMIT();
        compute_chunk32(sabs + (uint32_t)((c % STAGES) * BUF_BYTES), acc, lane, wm, wn);
    }

    // epilogue: + b1, relu, fp16 store
    const int g = lane >> 2, q = (lane & 3) * 2;
    const float* bp = b1 + (size_t)e * F_DIM + n0;
#pragma unroll
    for (int i = 0; i < 4; ++i) {
        const int r0 = m0 + wm * 64 + i * 16 + g;
        const size_t rowBase0 = ((size_t)e * C_CAP + r0) * F_DIM + n0;
        const size_t rowBase1 = rowBase0 + 8 * F_DIM;
#pragma unroll
        for (int j = 0; j < 4; ++j) {
            const int col = wn * 32 + j * 8 + q;
            const float bc0 = bp[col], bc1 = bp[col + 1];
            float v0 = fmaxf(acc[i][j][0] + bc0, 0.f);
            float v1 = fmaxf(acc[i][j][1] + bc1, 0.f);
            float v2 = fmaxf(acc[i][j][2] + bc0, 0.f);
            float v3 = fmaxf(acc[i][j][3] + bc1, 0.f);
            *reinterpret_cast<uint32_t*>(&g_hidden[rowBase0 + col]) =
                h2_u32(__floats2half2_rn(v0, v1));
            *reinterpret_cast<uint32_t*>(&g_hidden[rowBase1 + col]) =
                h2_u32(__floats2half2_rn(v2, v3));
        }
    }
}

// ---------------------------------------------------------------------------
// FFN2: out[tok] = gate * (hidden @ W2[e] + b2[e]);  K = F_DIM
// grid (H/128, C/128, E), 256 threads, 2 CTAs/SM
// ---------------------------------------------------------------------------
__global__ __launch_bounds__(256, 2)
void ffn2_mma(const float* __restrict__ b2, float* __restrict__ out) {
    extern __shared__ char dynsm[];
    __shared__ int   rowTok[128];
    __shared__ float rowGate[128];

    const uint32_t sabs = smem_u32(dynsm);
    const int tid = threadIdx.x, lane = tid & 31, wid = tid >> 5;
    const int wm = wid & 1, wn = wid >> 1;
    const int e = blockIdx.z, m0 = blockIdx.y * 128, n0 = blockIdx.x * 128;

    if (tid < 128) {
        int tk = g_slot_token[e * C_CAP + m0 + tid];
        rowTok[tid]  = tk;
        rowGate[tid] = (tk >= 0) ? g_gate[tk] : 0.0f;
    }
    __syncthreads();

    const int arow = tid >> 1, ac0 = (tid & 1) * 2;
    const __half* aSrc = g_hidden + ((size_t)e * C_CAP + m0 + arow) * F_DIM + ac0 * 8;
    const uint32_t aDst = (uint32_t)(arow * 80 + ac0 * 16);

    const int bk = tid >> 3, bc0 = (tid & 7) * 2;
    const size_t wBase = (size_t)e * F_DIM * H_DIM + n0;
    const uint32_t bD0 = B_OFF + (uint32_t)(bk * 256) + ((((uint32_t)bc0)      ^ ((uint32_t)bk & 7u)) << 4);
    const uint32_t bD1 = B_OFF + (uint32_t)(bk * 256) + ((((uint32_t)bc0 + 1u) ^ ((uint32_t)bk & 7u)) << 4);

    float acc[4][4][4];
#pragma unroll
    for (int i = 0; i < 4; i++)
#pragma unroll
        for (int j = 0; j < 4; j++)
#pragma unroll
            for (int r = 0; r < 4; r++) acc[i][j][r] = 0.0f;

    const int NCH = F_DIM / 32;   // 128

    auto load_stage = [&](int c) {
        const uint32_t bb = sabs + (uint32_t)((c % STAGES) * BUF_BYTES);
        const int kt = c * 32;
        CP16(bb + aDst,      aSrc + kt,     16u);
        CP16(bb + aDst + 16, aSrc + kt + 8, 16u);
        const size_t wrow = wBase + (size_t)(kt + bk) * H_DIM;
        CP16(bb + bD0, g_w2 + wrow + bc0 * 8,     16u);
        CP16(bb + bD1, g_w2 + wrow + bc0 * 8 + 8, 16u);
    };

    load_stage(0); CP_COMMIT();
    load_stage(1); CP_COMMIT();

    for (int c = 0; c < NCH; ++c) {
        CP_WAIT1();
        __syncthreads();
        if (c + 2 < NCH) load_stage(c + 2);
        CP_COMMIT();
        compute_chunk32(sabs + (uint32_t)((c % STAGES) * BUF_BYTES), acc, lane, wm, wn);
    }

    // epilogue: + b2, gate, scatter fp32
    const int g = lane >> 2, q = (lane & 3) * 2;
    const float* bp = b2 + (size_t)e * H_DIM + n0;
#pragma unroll
    for (int i = 0; i < 4; ++i) {
        const int rl0 = wm * 64 + i * 16 + g;
        const int rl1 = rl0 + 8;
        const int tok0 = rowTok[rl0], tok1 = rowTok[rl1];
        const float g0 = rowGate[rl0], g1 = rowGate[rl1];
#pragma unroll
        for (int j = 0; j < 4; ++j) {
            const int col = wn * 32 + j * 8 + q;
            const float bc0 = bp[col], bc1 = bp[col + 1];
            if (tok0 >= 0) {
                float2 o;
                o.x = g0 * (acc[i][j][0] + bc0);
                o.y = g0 * (acc[i][j][1] + bc1);
                *reinterpret_cast<float2*>(out + (size_t)tok0 * H_DIM + n0 + col) = o;
            }
            if (tok1 >= 0) {
                float2 o;
                o.x = g1 * (acc[i][j][2] + bc0);
                o.y = g1 * (acc[i][j][3] + bc1);
                *reinterpret_cast<float2*>(out + (size_t)tok1 * H_DIM + n0 + col) = o;
            }
        }
    }
}

// ---------------------------------------------------------------------------
// Launcher: weight converts forked to a 2nd stream (event fork/join, graph-
// capturable) so they overlap convX+gating+assign. FFN kernels identical R14.
// ---------------------------------------------------------------------------
extern "C" void kernel_launch(void* const* d_in, const int* in_sizes, int n_in,
                              void* d_out, int out_size) {
    const float* x  = (const float*)d_in[0];
    const float* Wg = (const float*)d_in[1];
    const float* W1 = (const float*)d_in[2];
    const float* b1 = (const float*)d_in[3];
    const float* W2 = (const float*)d_in[4];
    const float* b2 = (const float*)d_in[5];
    float* out = (float*)d_out;

    static cudaStream_t s2 = []() {
        cudaStream_t t;
        cudaStreamCreateWithFlags(&t, cudaStreamNonBlocking);
        return t;
    }();
    static cudaEvent_t evFork = []() {
        cudaEvent_t e;
        cudaEventCreateWithFlags(&e, cudaEventDisableTiming);
        return e;
    }();
    static cudaEvent_t evJoin = []() {
        cudaEvent_t e;
        cudaEventCreateWithFlags(&e, cudaEventDisableTiming);
        return e;
    }();

    cudaFuncSetAttribute(ffn1_mma, cudaFuncAttributeMaxDynamicSharedMemorySize, DYN_SMEM);
    cudaFuncSetAttribute(ffn2_mma, cudaFuncAttributeMaxDynamicSharedMemorySize, DYN_SMEM);

    cudaMemsetAsync(out, 0, (size_t)out_size * sizeof(float));

    __half *xp, *w1p, *w2p;
    cudaGetSymbolAddress((void**)&xp,  g_x16);
    cudaGetSymbolAddress((void**)&w1p, g_w1);
    cudaGetSymbolAddress((void**)&w2p, g_w2);

    const int nx = T_TOK * H_DIM / 8;
    const int nw = E_NUM * H_DIM * F_DIM / 8;

    // fork: weight converts on s2, concurrent with x-convert/gating/assign
    cudaEventRecord(evFork, 0);
    cudaStreamWaitEvent(s2, evFork, 0);
    convh_kernel<<<(nw + 255) / 256, 256, 0, s2>>>(W1, w1p, nw);
    convh_kernel<<<(nw + 255) / 256, 256, 0, s2>>>(W2, w2p, nw);
    cudaEventRecord(evJoin, s2);

    convh_kernel<<<(nx + 255) / 256, 256>>>(x, xp, nx);
    gating_kernel<<<T_TOK / 8, 256>>>(x, Wg);
    assign_kernel<<<1, 256>>>();

    // join before FFN1 consumes the converted weights
    cudaStreamWaitEvent(0, evJoin, 0);

    dim3 g1(F_DIM / 128, C_CAP / 128, E_NUM);   // (32, 8, 8)
    ffn1_mma<<<g1, 256, DYN_SMEM>>>(b1);

    dim3 g2(H_DIM / 128, C_CAP / 128, E_NUM);   // (8, 8, 8)
    ffn2_mma<<<g2, 256, DYN_SMEM>>>(b2, out);
}

// round 17
// speedup vs baseline: 1.0365x; 1.0029x over previous
#include <cuda_runtime.h>
#include <cuda_fp16.h>
#include <math.h>
#include <stdint.h>

// Problem constants
#define T_TOK 8192
#define H_DIM 1024
#define F_DIM 4096
#define E_NUM 8
#define C_CAP 1024

// ---------------------------------------------------------------------------
// Scratch
// ---------------------------------------------------------------------------
__device__ int    g_slot_token[E_NUM * C_CAP];
__device__ float  g_gate[T_TOK];
__device__ int    g_expert[T_TOK];
__device__ __half g_x16[(size_t)T_TOK * H_DIM];
__device__ __half g_w1[(size_t)E_NUM * H_DIM * F_DIM];
__device__ __half g_w2[(size_t)E_NUM * F_DIM * H_DIM];
__device__ __half g_hidden[(size_t)E_NUM * C_CAP * F_DIM];

// ---------------------------------------------------------------------------
// Helpers
// ---------------------------------------------------------------------------
__device__ __forceinline__ uint32_t smem_u32(const void* p) {
    uint32_t a;
    asm("{ .reg .u64 t; cvta.to.shared.u64 t, %1; cvt.u32.u64 %0, t; }" : "=r"(a) : "l"(p));
    return a;
}
__device__ __forceinline__ uint32_t h2_u32(__half2 h) {
    return *reinterpret_cast<uint32_t*>(&h);
}

#define LDSM_X4(r0, r1, r2, r3, addr) \
    asm volatile("ldmatrix.sync.aligned.m8n8.x4.shared.b16 {%0,%1,%2,%3}, [%4];" \
                 : "=r"(r0), "=r"(r1), "=r"(r2), "=r"(r3) : "r"(addr))
#define LDSM_X4_T(r0, r1, r2, r3, addr) \
    asm volatile("ldmatrix.sync.aligned.m8n8.x4.trans.shared.b16 {%0,%1,%2,%3}, [%4];" \
                 : "=r"(r0), "=r"(r1), "=r"(r2), "=r"(r3) : "r"(addr))

__device__ __forceinline__ void mma_fp16(float* d, const uint32_t* a,
                                         uint32_t b0, uint32_t b1) {
    asm volatile(
        "mma.sync.aligned.m16n8k16.row.col.f32.f16.f16.f32 "
        "{%0,%1,%2,%3},{%4,%5,%6,%7},{%8,%9},{%0,%1,%2,%3};"
        : "+f"(d[0]), "+f"(d[1]), "+f"(d[2]), "+f"(d[3])
        : "r"(a[0]), "r"(a[1]), "r"(a[2]), "r"(a[3]), "r"(b0), "r"(b1));
}

#define CP16(dst, src, sz) \
    asm volatile("cp.async.cg.shared.global [%0], [%1], 16, %2;" \
                 :: "r"(dst), "l"(src), "r"(sz))
#define CP_COMMIT() asm volatile("cp.async.commit_group;")
#define CP_WAIT1()  asm volatile("cp.async.wait_group 1;")

// SMEM stage (18 KB): A[128][80B] @0 (rows padded to 80B: LDSM phases
// conflict-free), B[32][256B] @10240 (XOR swizzle). 3 stages, wait_group 1.
#define A_OFF 0
#define B_OFF 10240
#define BUF_BYTES 18432
#define STAGES 3
#define DYN_SMEM (STAGES * BUF_BYTES)   // 55296

// ---------------------------------------------------------------------------
// Prep: fp32 -> fp16 convert (8 elems/thread)
// ---------------------------------------------------------------------------
__global__ __launch_bounds__(256) void convh_kernel(const float* __restrict__ src,
                                                    __half* __restrict__ dst,
                                                    int n8) {
    int i = blockIdx.x * blockDim.x + threadIdx.x;
    if (i >= n8) return;
    const float4* s = reinterpret_cast<const float4*>(src) + (size_t)i * 2;
    float4 v0 = s[0], v1 = s[1];
    uint4 o;
    o.x = h2_u32(__floats2half2_rn(v0.x, v0.y));
    o.y = h2_u32(__floats2half2_rn(v0.z, v0.w));
    o.z = h2_u32(__floats2half2_rn(v1.x, v1.y));
    o.w = h2_u32(__floats2half2_rn(v1.z, v1.w));
    reinterpret_cast<uint4*>(dst)[i] = o;
}

// ---------------------------------------------------------------------------
// Gating: one warp per token
// ---------------------------------------------------------------------------
__global__ __launch_bounds__(256) void gating_kernel(const float* __restrict__ x,
                                                     const float* __restrict__ Wg) {
    int warp = (blockIdx.x * blockDim.x + threadIdx.x) >> 5;
    int lane = threadIdx.x & 31;
    if (warp >= T_TOK) return;
    const float* xr = x + (size_t)warp * H_DIM;
    float acc[8];
#pragma unroll
    for (int e = 0; e < 8; e++) acc[e] = 0.0f;
    for (int h = lane; h < H_DIM; h += 32) {
        float xv = xr[h];
        const float4* w4 = reinterpret_cast<const float4*>(Wg + (size_t)h * E_NUM);
        float4 a = w4[0], b = w4[1];
        acc[0] += xv * a.x; acc[1] += xv * a.y; acc[2] += xv * a.z; acc[3] += xv * a.w;
        acc[4] += xv * b.x; acc[5] += xv * b.y; acc[6] += xv * b.z; acc[7] += xv * b.w;
    }
#pragma unroll
    for (int e = 0; e < 8; e++)
#pragma unroll
        for (int o = 16; o > 0; o >>= 1)
            acc[e] += __shfl_down_sync(0xffffffffu, acc[e], o);
    if (lane == 0) {
        float m = acc[0]; int am = 0;
#pragma unroll
        for (int e = 1; e < 8; e++)
            if (acc[e] > m) { m = acc[e]; am = e; }
        float s = 0.0f;
#pragma unroll
        for (int e = 0; e < 8; e++) s += expf(acc[e] - m);
        g_expert[warp] = am;
        g_gate[warp]   = 1.0f / s;
    }
}

// ---------------------------------------------------------------------------
// Assign: stable per-expert prefix scan (warp-parallel) + capacity drop
// ---------------------------------------------------------------------------
__global__ __launch_bounds__(256) void assign_kernel() {
    __shared__ int cnts[256][8];
    const int tid = threadIdx.x;
    for (int i = tid; i < E_NUM * C_CAP; i += 256) g_slot_token[i] = -1;
    const int per = T_TOK / 256, base = tid * per;
    int loc[8];
#pragma unroll
    for (int e = 0; e < 8; e++) loc[e] = 0;
    for (int j = 0; j < per; j++) loc[g_expert[base + j]]++;
#pragma unroll
    for (int e = 0; e < 8; e++) cnts[tid][e] = loc[e];
    __syncthreads();
    {   // warp w scans expert w's 256 chunk counts
        const int w = tid >> 5, lane = tid & 31;
        int run = 0;
#pragma unroll
        for (int b = 0; b < 8; ++b) {
            const int idx = b * 32 + lane;
            const int v = cnts[idx][w];
            int s = v;
#pragma unroll
            for (int o = 1; o < 32; o <<= 1) {
                int t = __shfl_up_sync(0xffffffffu, s, o);
                if (lane >= o) s += t;
            }
            cnts[idx][w] = run + s - v;
            run += __shfl_sync(0xffffffffu, s, 31);
        }
    }
    __syncthreads();
#pragma unroll
    for (int e = 0; e < 8; e++) loc[e] = cnts[tid][e];
    for (int j = 0; j < per; j++) {
        int t = base + j, e = g_expert[t], s = loc[e]++;
        if (s < C_CAP) g_slot_token[e * C_CAP + s] = t;
    }
}

// ---------------------------------------------------------------------------
// Compute one 32-K chunk: plain fp16 MMA, fp32 accumulate
// ---------------------------------------------------------------------------
__device__ __forceinline__ void compute_chunk32(uint32_t bufAbs, float acc[4][4][4],
                                                int lane, int wm, int wn) {
    const uint32_t sw = (uint32_t)(lane & 7);
    const uint32_t hl = (uint32_t)(lane >> 4);
    const uint32_t aBase = bufAbs + (uint32_t)((wm * 64 + (lane & 15)) * 80);
    const uint32_t bBase = bufAbs + B_OFF + (uint32_t)((lane & 15) * 256);
#pragma unroll
    for (int k16 = 0; k16 < 2; ++k16) {
        uint32_t bh[2][4];
#pragma unroll
        for (int j2 = 0; j2 < 2; ++j2) {
            const uint32_t csw = (((uint32_t)(wn * 4 + j2 * 2) + hl) ^ sw) << 4;
            LDSM_X4_T(bh[j2][0], bh[j2][1], bh[j2][2], bh[j2][3],
                      bBase + (uint32_t)(k16 * 4096) + csw);
        }
        const uint32_t hoff = ((uint32_t)(k16 * 2) + hl) << 4;
        uint32_t ah[4][4];
#pragma unroll
        for (int i = 0; i < 4; ++i) {
            const uint32_t aoff = (uint32_t)(i * 1280) + hoff;
            LDSM_X4(ah[i][0], ah[i][1], ah[i][2], ah[i][3], aBase + aoff);
        }
#pragma unroll
        for (int i = 0; i < 4; ++i)
#pragma unroll
            for (int j = 0; j < 4; ++j) {
                const uint32_t b0 = bh[j >> 1][(j & 1) * 2];
                const uint32_t b1 = bh[j >> 1][(j & 1) * 2 + 1];
                mma_fp16(acc[i][j], ah[i], b0, b1);
            }
    }
}

// ---------------------------------------------------------------------------
// FFN1: hidden(fp16) = relu(gather(x16) @ W1[e] + b1[e])
// grid (F/128, C/128, E), 256 threads, 2 CTAs/SM
// ---------------------------------------------------------------------------
__global__ __launch_bounds__(256, 2)
void ffn1_mma(const float* __restrict__ b1) {
    extern __shared__ char dynsm[];
    __shared__ int rowTok[128];

    const uint32_t sabs = smem_u32(dynsm);
    const int tid = threadIdx.x, lane = tid & 31, wid = tid >> 5;
    const int wm = wid & 1, wn = wid >> 1;
    const int e = blockIdx.z, m0 = blockIdx.y * 128, n0 = blockIdx.x * 128;

    if (tid < 128) rowTok[tid] = g_slot_token[e * C_CAP + m0 + tid];
    __syncthreads();

    const int arow = tid >> 1, ac0 = (tid & 1) * 2;
    const int atok = rowTok[arow];
    const uint32_t asz = (atok >= 0) ? 16u : 0u;
    const __half* aSrc = g_x16 + (size_t)(atok < 0 ? 0 : atok) * H_DIM + ac0 * 8;
    const uint32_t aDst = (uint32_t)(arow * 80 + ac0 * 16);

    const int bk = tid >> 3, bc0 = (tid & 7) * 2;
    const size_t wBase = (size_t)e * H_DIM * F_DIM + n0;
    const uint32_t bD0 = B_OFF + (uint32_t)(bk * 256) + ((((uint32_t)bc0)      ^ ((uint32_t)bk & 7u)) << 4);
    const uint32_t bD1 = B_OFF + (uint32_t)(bk * 256) + ((((uint32_t)bc0 + 1u) ^ ((uint32_t)bk & 7u)) << 4);

    float acc[4][4][4];
#pragma unroll
    for (int i = 0; i < 4; i++)
#pragma unroll
        for (int j = 0; j < 4; j++)
#pragma unroll
            for (int r = 0; r < 4; r++) acc[i][j][r] = 0.0f;

    const int NCH = H_DIM / 32;   // 32

    auto load_stage = [&](int c) {
        const uint32_t bb = sabs + (uint32_t)((c % STAGES) * BUF_BYTES);
        const int kt = c * 32;
        CP16(bb + aDst,      aSrc + kt,     asz);
        CP16(bb + aDst + 16, aSrc + kt + 8, asz);
        const size_t wrow = wBase + (size_t)(kt + bk) * F_DIM;
        CP16(bb + bD0, g_w1 + wrow + bc0 * 8,     16u);
        CP16(bb + bD1, g_w1 + wrow + bc0 * 8 + 8, 16u);
    };

    load_stage(0); CP_COMMIT();
    load_stage(1); CP_COMMIT();

    for (int c = 0; c < NCH; ++c) {
        CP_WAIT1();
        __syncthreads();
        if (c + 2 < NCH) load_stage(c + 2);
        CP_COMMIT();
        compute_chunk32(sabs + (uint32_t)((c % STAGES) * BUF_BYTES), acc, lane, wm, wn);
    }

    // epilogue: + b1, relu, fp16 store
    const int g = lane >> 2, q = (lane & 3) * 2;
    const float* bp = b1 + (size_t)e * F_DIM + n0;
#pragma unroll
    for (int i = 0; i < 4; ++i) {
        const int r0 = m0 + wm * 64 + i * 16 + g;
        const size_t rowBase0 = ((size_t)e * C_CAP + r0) * F_DIM + n0;
        const size_t rowBase1 = rowBase0 + 8 * F_DIM;
#pragma unroll
        for (int j = 0; j < 4; ++j) {
            const int col = wn * 32 + j * 8 + q;
            const float bc0 = bp[col], bc1 = bp[col + 1];
            float v0 = fmaxf(acc[i][j][0] + bc0, 0.f);
            float v1 = fmaxf(acc[i][j][1] + bc1, 0.f);
            float v2 = fmaxf(acc[i][j][2] + bc0, 0.f);
            float v3 = fmaxf(acc[i][j][3] + bc1, 0.f);
            *reinterpret_cast<uint32_t*>(&g_hidden[rowBase0 + col]) =
                h2_u32(__floats2half2_rn(v0, v1));
            *reinterpret_cast<uint32_t*>(&g_hidden[rowBase1 + col]) =
                h2_u32(__floats2half2_rn(v2, v3));
        }
    }
}

// ---------------------------------------------------------------------------
// FFN2: out[tok] = gate * (hidden @ W2[e] + b2[e]);  K = F_DIM
// grid (H/128, C/128, E), 256 threads, 2 CTAs/SM
// ---------------------------------------------------------------------------
__global__ __launch_bounds__(256, 2)
void ffn2_mma(const float* __restrict__ b2, float* __restrict__ out) {
    extern __shared__ char dynsm[];
    __shared__ int   rowTok[128];
    __shared__ float rowGate[128];

    const uint32_t sabs = smem_u32(dynsm);
    const int tid = threadIdx.x, lane = tid & 31, wid = tid >> 5;
    const int wm = wid & 1, wn = wid >> 1;
    const int e = blockIdx.z, m0 = blockIdx.y * 128, n0 = blockIdx.x * 128;

    if (tid < 128) {
        int tk = g_slot_token[e * C_CAP + m0 + tid];
        rowTok[tid]  = tk;
        rowGate[tid] = (tk >= 0) ? g_gate[tk] : 0.0f;
    }
    __syncthreads();

    const int arow = tid >> 1, ac0 = (tid & 1) * 2;
    const __half* aSrc = g_hidden + ((size_t)e * C_CAP + m0 + arow) * F_DIM + ac0 * 8;
    const uint32_t aDst = (uint32_t)(arow * 80 + ac0 * 16);

    const int bk = tid >> 3, bc0 = (tid & 7) * 2;
    const size_t wBase = (size_t)e * F_DIM * H_DIM + n0;
    const uint32_t bD0 = B_OFF + (uint32_t)(bk * 256) + ((((uint32_t)bc0)      ^ ((uint32_t)bk & 7u)) << 4);
    const uint32_t bD1 = B_OFF + (uint32_t)(bk * 256) + ((((uint32_t)bc0 + 1u) ^ ((uint32_t)bk & 7u)) << 4);

    float acc[4][4][4];
#pragma unroll
    for (int i = 0; i < 4; i++)
#pragma unroll
        for (int j = 0; j < 4; j++)
#pragma unroll
            for (int r = 0; r < 4; r++) acc[i][j][r] = 0.0f;

    const int NCH = F_DIM / 32;   // 128

    auto load_stage = [&](int c) {
        const uint32_t bb = sabs + (uint32_t)((c % STAGES) * BUF_BYTES);
        const int kt = c * 32;
        CP16(bb + aDst,      aSrc + kt,     16u);
        CP16(bb + aDst + 16, aSrc + kt + 8, 16u);
        const size_t wrow = wBase + (size_t)(kt + bk) * H_DIM;
        CP16(bb + bD0, g_w2 + wrow + bc0 * 8,     16u);
        CP16(bb + bD1, g_w2 + wrow + bc0 * 8 + 8, 16u);
    };

    load_stage(0); CP_COMMIT();
    load_stage(1); CP_COMMIT();

    for (int c = 0; c < NCH; ++c) {
        CP_WAIT1();
        __syncthreads();
        if (c + 2 < NCH) load_stage(c + 2);
        CP_COMMIT();
        compute_chunk32(sabs + (uint32_t)((c % STAGES) * BUF_BYTES), acc, lane, wm, wn);
    }

    // epilogue: + b2, gate, scatter fp32
    const int g = lane >> 2, q = (lane & 3) * 2;
    const float* bp = b2 + (size_t)e * H_DIM + n0;
#pragma unroll
    for (int i = 0; i < 4; ++i) {
        const int rl0 = wm * 64 + i * 16 + g;
        const int rl1 = rl0 + 8;
        const int tok0 = rowTok[rl0], tok1 = rowTok[rl1];
        const float g0 = rowGate[rl0], g1 = rowGate[rl1];
#pragma unroll
        for (int j = 0; j < 4; ++j) {
            const int col = wn * 32 + j * 8 + q;
            const float bc0 = bp[col], bc1 = bp[col + 1];
            if (tok0 >= 0) {
                float2 o;
                o.x = g0 * (acc[i][j][0] + bc0);
                o.y = g0 * (acc[i][j][1] + bc1);
                *reinterpret_cast<float2*>(out + (size_t)tok0 * H_DIM + n0 + col) = o;
            }
            if (tok1 >= 0) {
                float2 o;
                o.x = g1 * (acc[i][j][2] + bc0);
                o.y = g1 * (acc[i][j][3] + bc1);
                *reinterpret_cast<float2*>(out + (size_t)tok1 * H_DIM + n0 + col) = o;
            }
        }
    }
}

// ---------------------------------------------------------------------------
// Launcher: convW1 overlaps prefix; convW2 overlaps ffn1 (joins before ffn2).
// ---------------------------------------------------------------------------
extern "C" void kernel_launch(void* const* d_in, const int* in_sizes, int n_in,
                              void* d_out, int out_size) {
    const float* x  = (const float*)d_in[0];
    const float* Wg = (const float*)d_in[1];
    const float* W1 = (const float*)d_in[2];
    const float* b1 = (const float*)d_in[3];
    const float* W2 = (const float*)d_in[4];
    const float* b2 = (const float*)d_in[5];
    float* out = (float*)d_out;

    static cudaStream_t s2 = []() {
        cudaStream_t t;
        cudaStreamCreateWithFlags(&t, cudaStreamNonBlocking);
        return t;
    }();
    static cudaEvent_t evFork = []() {
        cudaEvent_t e;
        cudaEventCreateWithFlags(&e, cudaEventDisableTiming);
        return e;
    }();
    static cudaEvent_t evW1 = []() {
        cudaEvent_t e;
        cudaEventCreateWithFlags(&e, cudaEventDisableTiming);
        return e;
    }();
    static cudaEvent_t evW2 = []() {
        cudaEvent_t e;
        cudaEventCreateWithFlags(&e, cudaEventDisableTiming);
        return e;
    }();

    cudaFuncSetAttribute(ffn1_mma, cudaFuncAttributeMaxDynamicSharedMemorySize, DYN_SMEM);
    cudaFuncSetAttribute(ffn2_mma, cudaFuncAttributeMaxDynamicSharedMemorySize, DYN_SMEM);

    cudaMemsetAsync(out, 0, (size_t)out_size * sizeof(float));

    __half *xp, *w1p, *w2p;
    cudaGetSymbolAddress((void**)&xp,  g_x16);
    cudaGetSymbolAddress((void**)&w1p, g_w1);
    cudaGetSymbolAddress((void**)&w2p, g_w2);

    const int nx = T_TOK * H_DIM / 8;
    const int nw = E_NUM * H_DIM * F_DIM / 8;

    // fork: weight converts on s2
    cudaEventRecord(evFork, 0);
    cudaStreamWaitEvent(s2, evFork, 0);
    convh_kernel<<<(nw + 255) / 256, 256, 0, s2>>>(W1, w1p, nw);
    cudaEventRecord(evW1, s2);
    convh_kernel<<<(nw + 255) / 256, 256, 0, s2>>>(W2, w2p, nw);
    cudaEventRecord(evW2, s2);

    // main stream: x convert, gating, assign
    convh_kernel<<<(nx + 255) / 256, 256>>>(x, xp, nx);
    gating_kernel<<<T_TOK / 8, 256>>>(x, Wg);
    assign_kernel<<<1, 256>>>();

    // ffn1 needs W1 only; convW2 continues on s2 underneath ffn1
    cudaStreamWaitEvent(0, evW1, 0);
    dim3 g1(F_DIM / 128, C_CAP / 128, E_NUM);   // (32, 8, 8)
    ffn1_mma<<<g1, 256, DYN_SMEM>>>(b1);

    // ffn2 needs W2
    cudaStreamWaitEvent(0, evW2, 0);
    dim3 g2(H_DIM / 128, C_CAP / 128, E_NUM);   // (8, 8, 8)
    ffn2_mma<<<g2, 256, DYN_SMEM>>>(b2, out);
}